// round 2
// baseline (speedup 1.0000x reference)
#include <cuda_runtime.h>
#include <math.h>

#define THREADS 256
#define TILE 1024

// Scratch (no allocations allowed): projection constants + per-corner running min.
__device__ float g_proj[16];
__device__ unsigned int g_min[128];

// Robustly read a dimension that might arrive as int32/int64 or float32.
__device__ __forceinline__ double read_dim(const void* p) {
    int iv = *(const int*)p;                // little-endian: also low word of int64
    if (iv > 0 && iv < 1000000) return (double)iv;
    return (double)(*(const float*)p);      // fallback: stored as float
}

__global__ void k_setup(const float* __restrict__ cam,
                        const float* __restrict__ theta,
                        const float* __restrict__ va,
                        const void* hp, const void* wp) {
    // Match reference: radians = theta_f32 * f32(PI/180)  (fp32 rounding)
    const float d2rf = (float)(M_PI / 180.0);
    float rx = theta[0] * d2rf;
    float ry = theta[1] * d2rf;
    float rz = theta[2] * d2rf;
    double cx = cos((double)rx), sx = sin((double)rx);
    double cy = cos((double)ry), sy = sin((double)ry);
    double cz = cos((double)rz), sz = sin((double)rz);
    // M = Ry @ Rx ; R = Rz @ M   (computed in double, rounded once to fp32)
    double M00 = cy,  M01 = sy * sx, M02 = sy * cx;
    double M10 = 0.0, M11 = cx,      M12 = -sx;
    double M20 = -sy, M21 = cy * sx, M22 = cy * cx;
    double R00 = cz * M00 - sz * M10, R01 = cz * M01 - sz * M11, R02 = cz * M02 - sz * M12;
    double R10 = sz * M00 + cz * M10, R11 = sz * M01 + cz * M11, R12 = sz * M02 + cz * M12;

    double H = read_dim(hp), W = read_dim(wp);
    float vr = __fmul_rn(va[0] * 0.5f, d2rf);       // fp32 like reference
    double f = -H / (2.0 * tan((double)vr));

    g_proj[0] = (float)R00; g_proj[1] = (float)R01; g_proj[2] = (float)R02;
    g_proj[3] = (float)R10; g_proj[4] = (float)R11; g_proj[5] = (float)R12;
    g_proj[6] = (float)M20; g_proj[7] = (float)M21; g_proj[8] = (float)M22;
    g_proj[9]  = cam[0]; g_proj[10] = cam[1]; g_proj[11] = cam[2];
    g_proj[12] = (float)f;
    g_proj[13] = (float)(W * 0.5 - 0.5);   // cx0
    g_proj[14] = (float)(H * 0.5 - 0.5);   // cy0
    g_proj[15] = (float)H;
}

__global__ void k_init() {
    g_min[threadIdx.x] = 0xFFFFFFFFu;   // max key (monotone float encoding)
}

// Monotone total-order encoding of float -> unsigned (handles negatives).
__device__ __forceinline__ unsigned fenc(float f) {
    unsigned b = __float_as_uint(f);
    return (b & 0x80000000u) ? ~b : (b | 0x80000000u);
}

__global__ void __launch_bounds__(THREADS)
k_main(const float* __restrict__ P, const float* __restrict__ dtc, int N) {
    __shared__ float  raw[TILE * 3];
    __shared__ float4 sp[TILE];

    const int tid  = threadIdx.x;
    const int warp = tid >> 5;
    const int lane = tid & 31;

    const float R00 = g_proj[0], R01 = g_proj[1], R02 = g_proj[2];
    const float R10 = g_proj[3], R11 = g_proj[4], R12 = g_proj[5];
    const float R20 = g_proj[6], R21 = g_proj[7], R22 = g_proj[8];
    const float camx = g_proj[9], camy = g_proj[10], camz = g_proj[11];
    const float f    = g_proj[12];
    const float cx0  = g_proj[13], cy0 = g_proj[14], Hf = g_proj[15];

    // This warp owns 16 corners.
    float CX[16], CY[16], T1[16], m[16];
    const int cbase = warp * 16;
#pragma unroll
    for (int k = 0; k < 16; k++) {
        float ccx = dtc[2 * (cbase + k)];
        float ccy = dtc[2 * (cbase + k) + 1];
        CX[k] = ccx;
        CY[k] = ccy;
        // t1 = cx^2 + cy^2 with separate roundings (match jnp.sum(dtcCor**2, -1))
        T1[k] = __fadd_rn(__fmul_rn(ccx, ccx), __fmul_rn(ccy, ccy));
        m[k] = 3.4e38f;
    }

    const int tile0 = blockIdx.x * TILE;
    int nval = N - tile0; if (nval > TILE) nval = TILE;

    // Stage raw points (coalesced)
    const int lim = nval * 3;
    for (int i = tid; i < TILE * 3; i += THREADS)
        raw[i] = (i < lim) ? P[tile0 * 3 + i] : 0.0f;
    __syncthreads();

    // Project tile -> (u, v_final, s) replicating reference fp32 rounding.
    for (int i = tid; i < TILE; i += THREADS) {
        float px = raw[3 * i], py = raw[3 * i + 1], pz = raw[3 * i + 2];
        float tx = __fadd_rn(px, -camx);
        float ty = __fadd_rn(py, -camy);
        float tz = __fadd_rn(pz, -camz);
        // xyz = translated @ R.T  (fma-chain dot products)
        float x = __fmaf_rn(tz, R02, __fmaf_rn(ty, R01, __fmul_rn(tx, R00)));
        float y = __fmaf_rn(tz, R12, __fmaf_rn(ty, R11, __fmul_rn(tx, R10)));
        float z = __fmaf_rn(tz, R22, __fmaf_rn(ty, R21, __fmul_rn(tx, R20)));
        // perspective divide (true IEEE division like the reference)
        float xp = __fdiv_rn(x, z);
        float yp = __fdiv_rn(y, z);
        // uv = xyz_prime @ K.T ; third component is exactly 1 -> single fma
        float u  = __fmaf_rn(f, xp, cx0);
        float v  = __fmaf_rn(f, yp, cy0);
        float vf = __fadd_rn(Hf, -v);
        // s = u^2 + v^2 with separate roundings (match jnp.sum(uv_final**2, -1))
        float s  = __fadd_rn(__fmul_rn(u, u), __fmul_rn(vf, vf));
        if (i >= nval) { u = 0.0f; vf = 0.0f; s = 3.0e38f; }
        sp[i] = make_float4(u, vf, s, 0.0f);
    }
    __syncthreads();

    // Main loop: per pair, replicate d2 = (t1 + s) + (-2*dot) rounding:
    //   dot = fma(cy, v, rn(cx*u));  -2*dot is EXACT (power-of-2 scale);
    //   d2  = fma(-2, dot, rn(t1 + s))  == ((t1+s) - 2*dot) single-rounded.
#pragma unroll 2
    for (int i = lane; i < TILE; i += 32) {
        float4 q = sp[i];
        const float u = q.x, v = q.y, s = q.z;
#pragma unroll
        for (int k = 0; k < 16; k++) {
            float t1s = __fadd_rn(T1[k], s);
            float dot = __fmaf_rn(CY[k], v, __fmul_rn(CX[k], u));
            float d2  = __fmaf_rn(-2.0f, dot, t1s);
            m[k] = fminf(m[k], d2);
        }
    }

    // Warp butterfly reduce (lanes = point subsets, same corners)
#pragma unroll
    for (int off = 16; off >= 1; off >>= 1) {
#pragma unroll
        for (int k = 0; k < 16; k++)
            m[k] = fminf(m[k], __shfl_xor_sync(0xFFFFFFFFu, m[k], off));
    }

    if (lane == 0) {
#pragma unroll
        for (int k = 0; k < 16; k++)
            atomicMin(&g_min[cbase + k], fenc(m[k]));
    }
}

__global__ void k_final(float* __restrict__ out) {
    __shared__ float s[128];
    const int tid = threadIdx.x;
    unsigned k = g_min[tid];
    unsigned b = (k & 0x80000000u) ? (k ^ 0x80000000u) : ~k;
    s[tid] = __uint_as_float(b);
    __syncthreads();
    for (int off = 64; off > 0; off >>= 1) {
        if (tid < off) s[tid] += s[tid + off];
        __syncthreads();
    }
    if (tid == 0) out[0] = s[0];
}

extern "C" void kernel_launch(void* const* d_in, const int* in_sizes, int n_in,
                              void* d_out, int out_size) {
    const float* PntCld = (const float*)d_in[0];
    const float* dtcCor = (const float*)d_in[1];
    const float* cam    = (const float*)d_in[2];
    const float* theta  = (const float*)d_in[3];
    const float* va     = (const float*)d_in[4];
    const void*  hp     = d_in[5];
    const void*  wp     = d_in[6];

    int N = in_sizes[0] / 3;

    k_setup<<<1, 1>>>(cam, theta, va, hp, wp);
    k_init<<<1, 128>>>();
    int grid = (N + TILE - 1) / TILE;
    k_main<<<grid, THREADS>>>(PntCld, dtcCor, N);
    k_final<<<1, 128>>>((float*)d_out);
}

// round 3
// speedup vs baseline: 1.0504x; 1.0504x over previous
#include <cuda_runtime.h>
#include <math.h>

#define THREADS 256
#define SUB 512          // points staged per sub-tile
#define MAXBLK 296       // 2 * 148 SMs -> exactly one wave at occupancy 2

// Scratch (no device allocations allowed).
__device__ float g_proj[16];
__device__ float g_t1[128];
__device__ unsigned int g_min[128];
__device__ unsigned int g_ctr;

// Robustly read a dimension that might arrive as int32/int64 or float32.
__device__ __forceinline__ double read_dim(const void* p) {
    int iv = *(const int*)p;                // little-endian: also low word of int64
    if (iv > 0 && iv < 1000000) return (double)iv;
    return (double)(*(const float*)p);
}

// Monotone total-order encoding of float -> unsigned (handles negatives).
__device__ __forceinline__ unsigned fenc(float f) {
    unsigned b = __float_as_uint(f);
    return (b & 0x80000000u) ? ~b : (b | 0x80000000u);
}
__device__ __forceinline__ float fdec(unsigned k) {
    return __uint_as_float((k & 0x80000000u) ? (k ^ 0x80000000u) : ~k);
}

__device__ __forceinline__ unsigned long long pack2(float lo, float hi) {
    unsigned long long d;
    asm("mov.b64 %0, {%1, %2};" : "=l"(d) : "f"(lo), "f"(hi));
    return d;
}

// d2 for two corners at once, replicating reference rounding per lane:
//   t  = rn(t1 + s); p = rn(cx*u); dot = rn(cy*v + p); d2 = rn(-2*dot + t)
__device__ __forceinline__ void pair_d2(unsigned long long cx2, unsigned long long cy2,
                                        unsigned long long t12, unsigned long long uu,
                                        unsigned long long vv, unsigned long long ss,
                                        unsigned long long n2, float& d0, float& d1) {
    asm("{\n\t"
        ".reg .b64 t, p, d;\n\t"
        "add.rn.f32x2 t, %2, %3;\n\t"
        "mul.rn.f32x2 p, %4, %5;\n\t"
        "fma.rn.f32x2 d, %6, %7, p;\n\t"
        "fma.rn.f32x2 d, %8, d, t;\n\t"
        "mov.b64 {%0, %1}, d;\n\t"
        "}"
        : "=f"(d0), "=f"(d1)
        : "l"(t12), "l"(ss), "l"(cx2), "l"(uu), "l"(cy2), "l"(vv), "l"(n2));
}

__global__ void k_pre(const float* __restrict__ dtc,
                      const float* __restrict__ cam,
                      const float* __restrict__ theta,
                      const float* __restrict__ va,
                      const void* hp, const void* wp) {
    const int tid = threadIdx.x;
    g_min[tid] = 0xFFFFFFFFu;
    {
        float ccx = dtc[2 * tid], ccy = dtc[2 * tid + 1];
        g_t1[tid] = __fadd_rn(__fmul_rn(ccx, ccx), __fmul_rn(ccy, ccy));
    }
    if (tid == 0) {
        g_ctr = 0u;
        const float d2rf = (float)(M_PI / 180.0);
        float rx = theta[0] * d2rf, ry = theta[1] * d2rf, rz = theta[2] * d2rf;
        double cx = cos((double)rx), sx = sin((double)rx);
        double cy = cos((double)ry), sy = sin((double)ry);
        double cz = cos((double)rz), sz = sin((double)rz);
        double M01 = sy * sx, M02 = sy * cx;
        double M11 = cx,      M12 = -sx;
        double M20 = -sy, M21 = cy * sx, M22 = cy * cx;
        double R00 = cz * cy,          R01 = cz * M01 - sz * M11, R02 = cz * M02 - sz * M12;
        double R10 = sz * cy,          R11 = sz * M01 + cz * M11, R12 = sz * M02 + cz * M12;

        double H = read_dim(hp), W = read_dim(wp);
        float vr = __fmul_rn(va[0] * 0.5f, d2rf);
        double f = -H / (2.0 * tan((double)vr));

        g_proj[0] = (float)R00; g_proj[1] = (float)R01; g_proj[2] = (float)R02;
        g_proj[3] = (float)R10; g_proj[4] = (float)R11; g_proj[5] = (float)R12;
        g_proj[6] = (float)M20; g_proj[7] = (float)M21; g_proj[8] = (float)M22;
        g_proj[9]  = cam[0]; g_proj[10] = cam[1]; g_proj[11] = cam[2];
        g_proj[12] = (float)f;
        g_proj[13] = (float)(W * 0.5 - 0.5);   // cx0
        g_proj[14] = (float)(H * 0.5 - 0.5);   // cy0
        g_proj[15] = (float)H;
    }
}

__global__ void __launch_bounds__(THREADS, 2)
k_main(const float* __restrict__ P, const float* __restrict__ dtc, int N,
       float* __restrict__ out) {
    __shared__ float  raw[SUB * 3];
    __shared__ float4 sp[SUB];
    __shared__ bool   isLast;
    __shared__ float  red[128];

    const int tid  = threadIdx.x;
    const int warp = tid >> 5;
    const int lane = tid & 31;

    const float R00 = g_proj[0], R01 = g_proj[1], R02 = g_proj[2];
    const float R10 = g_proj[3], R11 = g_proj[4], R12 = g_proj[5];
    const float R20 = g_proj[6], R21 = g_proj[7], R22 = g_proj[8];
    const float camx = g_proj[9], camy = g_proj[10], camz = g_proj[11];
    const float f    = g_proj[12];
    const float kx0  = g_proj[13], ky0 = g_proj[14], Hf = g_proj[15];

    // This warp owns 16 corners, packed as 8 f32x2 pairs.
    unsigned long long CX2[8], CY2[8], T12[8];
    float m[16];
    const int cbase = warp * 16;
#pragma unroll
    for (int k = 0; k < 8; k++) {
        int c = cbase + 2 * k;
        CX2[k] = pack2(dtc[2 * c],     dtc[2 * c + 2]);
        CY2[k] = pack2(dtc[2 * c + 1], dtc[2 * c + 3]);
        T12[k] = pack2(g_t1[c], g_t1[c + 1]);
        m[2 * k] = 3.4e38f; m[2 * k + 1] = 3.4e38f;
    }
    const unsigned long long N2 = pack2(-2.0f, -2.0f);

    // Contiguous range for this block (even split across the fixed grid).
    const int ppb   = (N + gridDim.x - 1) / gridDim.x;
    const int start = blockIdx.x * ppb;
    const int stop  = min(N, start + ppb);

    for (int base = start; base < stop; base += SUB) {
        const int nval = min(SUB, stop - base);
        const int lim = nval * 3;
        for (int i = tid; i < SUB * 3; i += THREADS)
            raw[i] = (i < lim) ? P[base * 3 + i] : 0.0f;
        __syncthreads();

        for (int i = tid; i < SUB; i += THREADS) {
            float px = raw[3 * i], py = raw[3 * i + 1], pz = raw[3 * i + 2];
            float tx = __fadd_rn(px, -camx);
            float ty = __fadd_rn(py, -camy);
            float tz = __fadd_rn(pz, -camz);
            float x = __fmaf_rn(tz, R02, __fmaf_rn(ty, R01, __fmul_rn(tx, R00)));
            float y = __fmaf_rn(tz, R12, __fmaf_rn(ty, R11, __fmul_rn(tx, R10)));
            float z = __fmaf_rn(tz, R22, __fmaf_rn(ty, R21, __fmul_rn(tx, R20)));
            float xp = __fdiv_rn(x, z);
            float yp = __fdiv_rn(y, z);
            float u  = __fmaf_rn(f, xp, kx0);
            float v  = __fmaf_rn(f, yp, ky0);
            float vf = __fadd_rn(Hf, -v);
            float s  = __fadd_rn(__fmul_rn(u, u), __fmul_rn(vf, vf));
            if (i >= nval) { u = 0.0f; vf = 0.0f; s = 3.0e38f; }
            sp[i] = make_float4(u, vf, s, 0.0f);
        }
        __syncthreads();

#pragma unroll 2
        for (int i = lane; i < SUB; i += 32) {
            float4 q = sp[i];
            unsigned long long uu = pack2(q.x, q.x);
            unsigned long long vv = pack2(q.y, q.y);
            unsigned long long ss = pack2(q.z, q.z);
#pragma unroll
            for (int k = 0; k < 8; k++) {
                float d0, d1;
                pair_d2(CX2[k], CY2[k], T12[k], uu, vv, ss, N2, d0, d1);
                m[2 * k]     = fminf(m[2 * k],     d0);
                m[2 * k + 1] = fminf(m[2 * k + 1], d1);
            }
        }
        __syncthreads();
    }

    // Warp butterfly reduce (lanes hold disjoint point subsets, same corners).
#pragma unroll
    for (int off = 16; off >= 1; off >>= 1) {
#pragma unroll
        for (int k = 0; k < 16; k++)
            m[k] = fminf(m[k], __shfl_xor_sync(0xFFFFFFFFu, m[k], off));
    }
    if (lane == 0) {
#pragma unroll
        for (int k = 0; k < 16; k++)
            atomicMin(&g_min[cbase + k], fenc(m[k]));
    }

    // Last block to finish performs the final deterministic sum.
    __threadfence();
    __syncthreads();
    if (tid == 0) {
        unsigned old = atomicAdd(&g_ctr, 1u);
        isLast = (old == gridDim.x - 1u);
    }
    __syncthreads();
    if (isLast) {
        if (tid < 128) red[tid] = fdec(g_min[tid]);
        __syncthreads();
        for (int off = 64; off > 0; off >>= 1) {
            if (tid < off) red[tid] += red[tid + off];
            __syncthreads();
        }
        if (tid == 0) out[0] = red[0];
    }
}

extern "C" void kernel_launch(void* const* d_in, const int* in_sizes, int n_in,
                              void* d_out, int out_size) {
    const float* PntCld = (const float*)d_in[0];
    const float* dtcCor = (const float*)d_in[1];
    const float* cam    = (const float*)d_in[2];
    const float* theta  = (const float*)d_in[3];
    const float* va     = (const float*)d_in[4];
    const void*  hp     = d_in[5];
    const void*  wp     = d_in[6];

    int N = in_sizes[0] / 3;

    k_pre<<<1, 128>>>(dtcCor, cam, theta, va, hp, wp);
    int grid = (N + SUB - 1) / SUB;
    if (grid > MAXBLK) grid = MAXBLK;
    if (grid < 1) grid = 1;
    k_main<<<grid, THREADS>>>(PntCld, dtcCor, N, (float*)d_out);
}

// round 4
// speedup vs baseline: 1.1242x; 1.0703x over previous
#include <cuda_runtime.h>
#include <math.h>

#define THREADS 256
#define SUB 512           // points staged per sub-tile
#define GRID 444          // 3 * 148 SMs -> one wave at occupancy 3
#define NRANGE (GRID / 2) // point ranges (each range served by 2 corner-half blocks)

// Scratch (no device allocations allowed).
__device__ float g_proj[16];
__device__ float g_t1[128];
__device__ unsigned int g_min[128];
__device__ unsigned int g_ctr;

// Robustly read a dimension that might arrive as int32/int64 or float32.
__device__ __forceinline__ double read_dim(const void* p) {
    int iv = *(const int*)p;                // little-endian: also low word of int64
    if (iv > 0 && iv < 1000000) return (double)iv;
    return (double)(*(const float*)p);
}

// Monotone total-order encoding of float -> unsigned (handles negatives).
__device__ __forceinline__ unsigned fenc(float f) {
    unsigned b = __float_as_uint(f);
    return (b & 0x80000000u) ? ~b : (b | 0x80000000u);
}
__device__ __forceinline__ float fdec(unsigned k) {
    return __uint_as_float((k & 0x80000000u) ? (k ^ 0x80000000u) : ~k);
}

__device__ __forceinline__ unsigned long long pack2(float lo, float hi) {
    unsigned long long d;
    asm("mov.b64 %0, {%1, %2};" : "=l"(d) : "f"(lo), "f"(hi));
    return d;
}

// d2 for two corners at once, replicating reference rounding per lane:
//   t  = rn(t1 + s); p = rn(cx*u); dot = rn(cy*v + p); d2 = rn(-2*dot + t)
__device__ __forceinline__ void pair_d2(unsigned long long cx2, unsigned long long cy2,
                                        unsigned long long t12, unsigned long long uu,
                                        unsigned long long vv, unsigned long long ss,
                                        unsigned long long n2, float& d0, float& d1) {
    asm("{\n\t"
        ".reg .b64 t, p, d;\n\t"
        "add.rn.f32x2 t, %2, %3;\n\t"
        "mul.rn.f32x2 p, %4, %5;\n\t"
        "fma.rn.f32x2 d, %6, %7, p;\n\t"
        "fma.rn.f32x2 d, %8, d, t;\n\t"
        "mov.b64 {%0, %1}, d;\n\t"
        "}"
        : "=f"(d0), "=f"(d1)
        : "l"(t12), "l"(ss), "l"(cx2), "l"(uu), "l"(cy2), "l"(vv), "l"(n2));
}

__global__ void k_pre(const float* __restrict__ dtc,
                      const float* __restrict__ cam,
                      const float* __restrict__ theta,
                      const float* __restrict__ va,
                      const void* hp, const void* wp) {
    const int tid = threadIdx.x;
    g_min[tid] = 0xFFFFFFFFu;
    {
        float ccx = dtc[2 * tid], ccy = dtc[2 * tid + 1];
        g_t1[tid] = __fadd_rn(__fmul_rn(ccx, ccx), __fmul_rn(ccy, ccy));
    }
    if (tid == 0) {
        g_ctr = 0u;
        const float d2rf = (float)(M_PI / 180.0);
        float rx = theta[0] * d2rf, ry = theta[1] * d2rf, rz = theta[2] * d2rf;
        double cx = cos((double)rx), sx = sin((double)rx);
        double cy = cos((double)ry), sy = sin((double)ry);
        double cz = cos((double)rz), sz = sin((double)rz);
        double M01 = sy * sx, M02 = sy * cx;
        double M11 = cx,      M12 = -sx;
        double M20 = -sy, M21 = cy * sx, M22 = cy * cx;
        double R00 = cz * cy, R01 = cz * M01 - sz * M11, R02 = cz * M02 - sz * M12;
        double R10 = sz * cy, R11 = sz * M01 + cz * M11, R12 = sz * M02 + cz * M12;

        double H = read_dim(hp), W = read_dim(wp);
        float vr = __fmul_rn(va[0] * 0.5f, d2rf);
        double f = -H / (2.0 * tan((double)vr));

        g_proj[0] = (float)R00; g_proj[1] = (float)R01; g_proj[2] = (float)R02;
        g_proj[3] = (float)R10; g_proj[4] = (float)R11; g_proj[5] = (float)R12;
        g_proj[6] = (float)M20; g_proj[7] = (float)M21; g_proj[8] = (float)M22;
        g_proj[9]  = cam[0]; g_proj[10] = cam[1]; g_proj[11] = cam[2];
        g_proj[12] = (float)f;
        g_proj[13] = (float)(W * 0.5 - 0.5);   // cx0
        g_proj[14] = (float)(H * 0.5 - 0.5);   // cy0
        g_proj[15] = (float)H;
    }
}

__global__ void __launch_bounds__(THREADS, 3)
k_main(const float* __restrict__ P, const float* __restrict__ dtc, int N,
       float* __restrict__ out) {
    __shared__ float  raw[SUB * 3];
    __shared__ float4 sp[SUB];
    __shared__ bool   isLast;
    __shared__ float  red[128];

    const int tid  = threadIdx.x;
    const int warp = tid >> 5;
    const int lane = tid & 31;

    const int range = blockIdx.x >> 1;     // which point range
    const int chalf = blockIdx.x & 1;      // which 64-corner half

    const float R00 = g_proj[0], R01 = g_proj[1], R02 = g_proj[2];
    const float R10 = g_proj[3], R11 = g_proj[4], R12 = g_proj[5];
    const float R20 = g_proj[6], R21 = g_proj[7], R22 = g_proj[8];
    const float camx = g_proj[9], camy = g_proj[10], camz = g_proj[11];
    const float f    = g_proj[12];
    const float kx0  = g_proj[13], ky0 = g_proj[14], Hf = g_proj[15];

    // This warp owns 8 corners, packed as 4 f32x2 pairs. (32 hot regs)
    unsigned long long CX2[4], CY2[4], T12[4];
    float m[8];
    const int cbase = chalf * 64 + warp * 8;
#pragma unroll
    for (int k = 0; k < 4; k++) {
        int c = cbase + 2 * k;
        CX2[k] = pack2(dtc[2 * c],     dtc[2 * c + 2]);
        CY2[k] = pack2(dtc[2 * c + 1], dtc[2 * c + 3]);
        T12[k] = pack2(g_t1[c], g_t1[c + 1]);
        m[2 * k] = 3.4e38f; m[2 * k + 1] = 3.4e38f;
    }
    const unsigned long long N2 = pack2(-2.0f, -2.0f);

    // Contiguous point range for this block pair.
    const int ppb   = (N + NRANGE - 1) / NRANGE;
    const int start = range * ppb;
    const int stop  = min(N, start + ppb);

    for (int base = start; base < stop; base += SUB) {
        const int nval = min(SUB, stop - base);
        const int lim = nval * 3;
        for (int i = tid; i < SUB * 3; i += THREADS)
            raw[i] = (i < lim) ? P[base * 3 + i] : 0.0f;
        __syncthreads();

        for (int i = tid; i < SUB; i += THREADS) {
            float px = raw[3 * i], py = raw[3 * i + 1], pz = raw[3 * i + 2];
            float tx = __fadd_rn(px, -camx);
            float ty = __fadd_rn(py, -camy);
            float tz = __fadd_rn(pz, -camz);
            float x = __fmaf_rn(tz, R02, __fmaf_rn(ty, R01, __fmul_rn(tx, R00)));
            float y = __fmaf_rn(tz, R12, __fmaf_rn(ty, R11, __fmul_rn(tx, R10)));
            float z = __fmaf_rn(tz, R22, __fmaf_rn(ty, R21, __fmul_rn(tx, R20)));
            float xp = __fdiv_rn(x, z);
            float yp = __fdiv_rn(y, z);
            float u  = __fmaf_rn(f, xp, kx0);
            float v  = __fmaf_rn(f, yp, ky0);
            float vf = __fadd_rn(Hf, -v);
            float s  = __fadd_rn(__fmul_rn(u, u), __fmul_rn(vf, vf));
            if (i >= nval) { u = 0.0f; vf = 0.0f; s = 3.0e38f; }
            sp[i] = make_float4(u, vf, s, 0.0f);
        }
        __syncthreads();

#pragma unroll 4
        for (int i = lane; i < SUB; i += 32) {
            float4 q = sp[i];
            unsigned long long uu = pack2(q.x, q.x);
            unsigned long long vv = pack2(q.y, q.y);
            unsigned long long ss = pack2(q.z, q.z);
#pragma unroll
            for (int k = 0; k < 4; k++) {
                float d0, d1;
                pair_d2(CX2[k], CY2[k], T12[k], uu, vv, ss, N2, d0, d1);
                m[2 * k]     = fminf(m[2 * k],     d0);
                m[2 * k + 1] = fminf(m[2 * k + 1], d1);
            }
        }
        __syncthreads();
    }

    // Warp butterfly reduce (lanes hold disjoint point subsets, same corners).
#pragma unroll
    for (int off = 16; off >= 1; off >>= 1) {
#pragma unroll
        for (int k = 0; k < 8; k++)
            m[k] = fminf(m[k], __shfl_xor_sync(0xFFFFFFFFu, m[k], off));
    }
    if (lane == 0) {
#pragma unroll
        for (int k = 0; k < 8; k++)
            atomicMin(&g_min[cbase + k], fenc(m[k]));
    }

    // Last block to finish performs the final deterministic sum.
    __threadfence();
    __syncthreads();
    if (tid == 0) {
        unsigned old = atomicAdd(&g_ctr, 1u);
        isLast = (old == gridDim.x - 1u);
    }
    __syncthreads();
    if (isLast) {
        if (tid < 128) red[tid] = fdec(g_min[tid]);
        __syncthreads();
        for (int off = 64; off > 0; off >>= 1) {
            if (tid < off) red[tid] += red[tid + off];
            __syncthreads();
        }
        if (tid == 0) out[0] = red[0];
    }
}

extern "C" void kernel_launch(void* const* d_in, const int* in_sizes, int n_in,
                              void* d_out, int out_size) {
    const float* PntCld = (const float*)d_in[0];
    const float* dtcCor = (const float*)d_in[1];
    const float* cam    = (const float*)d_in[2];
    const float* theta  = (const float*)d_in[3];
    const float* va     = (const float*)d_in[4];
    const void*  hp     = d_in[5];
    const void*  wp     = d_in[6];

    int N = in_sizes[0] / 3;

    k_pre<<<1, 128>>>(dtcCor, cam, theta, va, hp, wp);
    k_main<<<GRID, THREADS>>>(PntCld, dtcCor, N, (float*)d_out);
}

// round 5
// speedup vs baseline: 1.1870x; 1.0559x over previous
#include <cuda_runtime.h>
#include <math.h>

#define THREADS 256
#define SUB 512           // points staged per sub-tile
#define GRID 444          // 3 * 148 SMs -> one wave at occupancy 3
#define NRANGE (GRID / 2) // point ranges (each range served by 2 corner-half blocks)

// Scratch (no device allocations allowed).
__device__ float g_proj[16];
__device__ float g_t1[128];
__device__ unsigned int g_min[128];
__device__ unsigned int g_ctr;

// Robustly read a dimension that might arrive as int32/int64 or float32.
__device__ __forceinline__ double read_dim(const void* p) {
    int iv = *(const int*)p;                // little-endian: also low word of int64
    if (iv > 0 && iv < 1000000) return (double)iv;
    return (double)(*(const float*)p);
}

// Monotone total-order encoding of float -> unsigned (handles negatives).
__device__ __forceinline__ unsigned fenc(float f) {
    unsigned b = __float_as_uint(f);
    return (b & 0x80000000u) ? ~b : (b | 0x80000000u);
}
__device__ __forceinline__ float fdec(unsigned k) {
    return __uint_as_float((k & 0x80000000u) ? (k ^ 0x80000000u) : ~k);
}

__device__ __forceinline__ unsigned long long pack2(float lo, float hi) {
    unsigned long long d;
    asm("mov.b64 %0, {%1, %2};" : "=l"(d) : "f"(lo), "f"(hi));
    return d;
}
__device__ __forceinline__ void unpack2(unsigned long long d, float& lo, float& hi) {
    asm("mov.b64 {%0, %1}, %2;" : "=f"(lo), "=f"(hi) : "l"(d));
}

// One corner vs two points, replicating reference per-lane rounding:
//   t = rn(t1+s); p = rn(cx*u); d = rn(cy*v + p); d2 = rn(-2*d + t); m = min(m, d2)
// All mov.b64 splits/joins are register renames (eliminated by ptxas).
__device__ __forceinline__ void corner_step(unsigned long long& m2,
                                            unsigned long long t12,
                                            unsigned long long cx2,
                                            unsigned long long cy2,
                                            unsigned long long u2,
                                            unsigned long long v2,
                                            unsigned long long s2,
                                            unsigned long long n2) {
    asm("{\n\t"
        ".reg .b64 t, p, d;\n\t"
        ".reg .f32 dlo, dhi, mlo, mhi;\n\t"
        "add.rn.f32x2 t, %1, %2;\n\t"
        "mul.rn.f32x2 p, %3, %4;\n\t"
        "fma.rn.f32x2 d, %5, %6, p;\n\t"
        "fma.rn.f32x2 d, %7, d, t;\n\t"
        "mov.b64 {dlo, dhi}, d;\n\t"
        "mov.b64 {mlo, mhi}, %0;\n\t"
        "min.f32 mlo, mlo, dlo;\n\t"
        "min.f32 mhi, mhi, dhi;\n\t"
        "mov.b64 %0, {mlo, mhi};\n\t"
        "}"
        : "+l"(m2)
        : "l"(t12), "l"(s2), "l"(cx2), "l"(u2), "l"(cy2), "l"(v2), "l"(n2));
}

__global__ void k_pre(const float* __restrict__ dtc,
                      const float* __restrict__ cam,
                      const float* __restrict__ theta,
                      const float* __restrict__ va,
                      const void* hp, const void* wp) {
    const int tid = threadIdx.x;
    g_min[tid] = 0xFFFFFFFFu;
    {
        float ccx = dtc[2 * tid], ccy = dtc[2 * tid + 1];
        g_t1[tid] = __fadd_rn(__fmul_rn(ccx, ccx), __fmul_rn(ccy, ccy));
    }
    if (tid == 0) {
        g_ctr = 0u;
        const float d2rf = (float)(M_PI / 180.0);
        float rx = theta[0] * d2rf, ry = theta[1] * d2rf, rz = theta[2] * d2rf;
        double cx = cos((double)rx), sx = sin((double)rx);
        double cy = cos((double)ry), sy = sin((double)ry);
        double cz = cos((double)rz), sz = sin((double)rz);
        double M01 = sy * sx, M02 = sy * cx;
        double M11 = cx,      M12 = -sx;
        double M20 = -sy, M21 = cy * sx, M22 = cy * cx;
        double R00 = cz * cy, R01 = cz * M01 - sz * M11, R02 = cz * M02 - sz * M12;
        double R10 = sz * cy, R11 = sz * M01 + cz * M11, R12 = sz * M02 + cz * M12;

        double H = read_dim(hp), W = read_dim(wp);
        float vr = __fmul_rn(va[0] * 0.5f, d2rf);
        double f = -H / (2.0 * tan((double)vr));

        g_proj[0] = (float)R00; g_proj[1] = (float)R01; g_proj[2] = (float)R02;
        g_proj[3] = (float)R10; g_proj[4] = (float)R11; g_proj[5] = (float)R12;
        g_proj[6] = (float)M20; g_proj[7] = (float)M21; g_proj[8] = (float)M22;
        g_proj[9]  = cam[0]; g_proj[10] = cam[1]; g_proj[11] = cam[2];
        g_proj[12] = (float)f;
        g_proj[13] = (float)(W * 0.5 - 0.5);   // cx0
        g_proj[14] = (float)(H * 0.5 - 0.5);   // cy0
        g_proj[15] = (float)H;
    }
}

__global__ void __launch_bounds__(THREADS, 3)
k_main(const float* __restrict__ P, const float* __restrict__ dtc, int N,
       float* __restrict__ out) {
    __shared__ __align__(16) float su[SUB];
    __shared__ __align__(16) float sv[SUB];
    __shared__ __align__(16) float ss[SUB];
    __shared__ bool  isLast;
    __shared__ float red[128];

    const int tid  = threadIdx.x;
    const int warp = tid >> 5;
    const int lane = tid & 31;

    const int range = blockIdx.x >> 1;     // which point range
    const int chalf = blockIdx.x & 1;      // which 64-corner half

    // This warp owns 8 corners as splatted f32x2 constants; packed running min.
    unsigned long long CX2[8], CY2[8], T12[8], M2[8];
    const int cbase = chalf * 64 + warp * 8;
#pragma unroll
    for (int k = 0; k < 8; k++) {
        int c = cbase + k;
        float ccx = dtc[2 * c], ccy = dtc[2 * c + 1];
        CX2[k] = pack2(ccx, ccx);
        CY2[k] = pack2(ccy, ccy);
        float t1 = g_t1[c];
        T12[k] = pack2(t1, t1);
        M2[k]  = pack2(3.4e38f, 3.4e38f);
    }
    const unsigned long long N2 = pack2(-2.0f, -2.0f);

    // Contiguous point range for this block pair.
    const int ppb   = (N + NRANGE - 1) / NRANGE;
    const int start = range * ppb;
    const int stop  = min(N, start + ppb);

    for (int base = start; base < stop; base += SUB) {
        const int nval = min(SUB, stop - base);

        // Project directly from gmem (coalesced 384B/warp; L2-resident).
        for (int i = tid; i < SUB; i += THREADS) {
            float u = 0.0f, vf = 0.0f, s = 3.0e38f;
            if (i < nval) {
                const float* pp = P + 3 * (base + i);
                float px = pp[0], py = pp[1], pz = pp[2];
                float tx = __fadd_rn(px, -g_proj[9]);
                float ty = __fadd_rn(py, -g_proj[10]);
                float tz = __fadd_rn(pz, -g_proj[11]);
                float x = __fmaf_rn(tz, g_proj[2], __fmaf_rn(ty, g_proj[1], __fmul_rn(tx, g_proj[0])));
                float y = __fmaf_rn(tz, g_proj[5], __fmaf_rn(ty, g_proj[4], __fmul_rn(tx, g_proj[3])));
                float z = __fmaf_rn(tz, g_proj[8], __fmaf_rn(ty, g_proj[7], __fmul_rn(tx, g_proj[6])));
                float xp = __fdiv_rn(x, z);
                float yp = __fdiv_rn(y, z);
                u  = __fmaf_rn(g_proj[12], xp, g_proj[13]);
                float v = __fmaf_rn(g_proj[12], yp, g_proj[14]);
                vf = __fadd_rn(g_proj[15], -v);
                s  = __fadd_rn(__fmul_rn(u, u), __fmul_rn(vf, vf));
            }
            su[i] = u; sv[i] = vf; ss[i] = s;
        }
        __syncthreads();

        // Inner loop: 2 points per iteration, zero pack overhead.
        const unsigned long long* u64 = (const unsigned long long*)su;
        const unsigned long long* v64 = (const unsigned long long*)sv;
        const unsigned long long* s64 = (const unsigned long long*)ss;
#pragma unroll 2
        for (int j = lane; j < SUB / 2; j += 32) {
            unsigned long long u2 = u64[j];
            unsigned long long v2 = v64[j];
            unsigned long long s2 = s64[j];
#pragma unroll
            for (int k = 0; k < 8; k++)
                corner_step(M2[k], T12[k], CX2[k], CY2[k], u2, v2, s2, N2);
        }
        __syncthreads();
    }

    // Merge packed halves (even/odd points), then warp butterfly reduce.
    float m[8];
#pragma unroll
    for (int k = 0; k < 8; k++) {
        float lo, hi;
        unpack2(M2[k], lo, hi);
        m[k] = fminf(lo, hi);
    }
#pragma unroll
    for (int off = 16; off >= 1; off >>= 1) {
#pragma unroll
        for (int k = 0; k < 8; k++)
            m[k] = fminf(m[k], __shfl_xor_sync(0xFFFFFFFFu, m[k], off));
    }
    if (lane == 0) {
#pragma unroll
        for (int k = 0; k < 8; k++)
            atomicMin(&g_min[cbase + k], fenc(m[k]));
    }

    // Last block to finish performs the final deterministic sum.
    __threadfence();
    __syncthreads();
    if (tid == 0) {
        unsigned old = atomicAdd(&g_ctr, 1u);
        isLast = (old == gridDim.x - 1u);
    }
    __syncthreads();
    if (isLast) {
        if (tid < 128) red[tid] = fdec(g_min[tid]);
        __syncthreads();
        for (int off = 64; off > 0; off >>= 1) {
            if (tid < off) red[tid] += red[tid + off];
            __syncthreads();
        }
        if (tid == 0) out[0] = red[0];
    }
}

extern "C" void kernel_launch(void* const* d_in, const int* in_sizes, int n_in,
                              void* d_out, int out_size) {
    const float* PntCld = (const float*)d_in[0];
    const float* dtcCor = (const float*)d_in[1];
    const float* cam    = (const float*)d_in[2];
    const float* theta  = (const float*)d_in[3];
    const float* va     = (const float*)d_in[4];
    const void*  hp     = d_in[5];
    const void*  wp     = d_in[6];

    int N = in_sizes[0] / 3;

    k_pre<<<1, 128>>>(dtcCor, cam, theta, va, hp, wp);
    k_main<<<GRID, THREADS>>>(PntCld, dtcCor, N, (float*)d_out);
}

// round 6
// speedup vs baseline: 1.6245x; 1.3686x over previous
#include <cuda_runtime.h>
#include <math.h>

#define THREADS 256
#define SUB 512           // points staged per sub-tile
#define GRID 444          // 3 * 148 SMs -> one wave at occupancy 3
#define NRANGE (GRID / 2) // point ranges (each range served by 2 corner-half blocks)

// Zero-initialized scratch; kernel self-restores zeros after each run
// (graph-replay deterministic, no init kernel needed).
__device__ unsigned int g_cmax[128];  // key = ~fenc(min d2) ; 0 == "empty"
__device__ unsigned int g_ctr;

// Robustly read a dimension that might arrive as int32/int64 or float32.
__device__ __forceinline__ float read_dim(const void* p) {
    int iv = *(const int*)p;                // little-endian: also low word of int64
    if (iv > 0 && iv < 1000000) return (float)iv;
    return *(const float*)p;
}

// Monotone total-order encoding of float -> unsigned (handles negatives).
__device__ __forceinline__ unsigned fenc(float f) {
    unsigned b = __float_as_uint(f);
    return (b & 0x80000000u) ? ~b : (b | 0x80000000u);
}
__device__ __forceinline__ float fdec(unsigned k) {
    return __uint_as_float((k & 0x80000000u) ? (k ^ 0x80000000u) : ~k);
}

__device__ __forceinline__ unsigned long long pack2(float lo, float hi) {
    unsigned long long d;
    asm("mov.b64 %0, {%1, %2};" : "=l"(d) : "f"(lo), "f"(hi));
    return d;
}
__device__ __forceinline__ void unpack2(unsigned long long d, float& lo, float& hi) {
    asm("mov.b64 {%0, %1}, %2;" : "=f"(lo), "=f"(hi) : "l"(d));
}

// One corner vs two points, replicating reference per-lane rounding:
//   t = rn(t1+s); p = rn(cx*u); d = rn(cy*v + p); d2 = rn(-2*d + t); m = min(m, d2)
__device__ __forceinline__ void corner_step(unsigned long long& m2,
                                            unsigned long long t12,
                                            unsigned long long cx2,
                                            unsigned long long cy2,
                                            unsigned long long u2,
                                            unsigned long long v2,
                                            unsigned long long s2,
                                            unsigned long long n2) {
    asm("{\n\t"
        ".reg .b64 t, p, d;\n\t"
        ".reg .f32 dlo, dhi, mlo, mhi;\n\t"
        "add.rn.f32x2 t, %1, %2;\n\t"
        "mul.rn.f32x2 p, %3, %4;\n\t"
        "fma.rn.f32x2 d, %5, %6, p;\n\t"
        "fma.rn.f32x2 d, %7, d, t;\n\t"
        "mov.b64 {dlo, dhi}, d;\n\t"
        "mov.b64 {mlo, mhi}, %0;\n\t"
        "min.f32 mlo, mlo, dlo;\n\t"
        "min.f32 mhi, mhi, dhi;\n\t"
        "mov.b64 %0, {mlo, mhi};\n\t"
        "}"
        : "+l"(m2)
        : "l"(t12), "l"(s2), "l"(cx2), "l"(u2), "l"(cy2), "l"(v2), "l"(n2));
}

__global__ void __launch_bounds__(THREADS, 3)
k_main(const float* __restrict__ P, const float* __restrict__ dtc,
       const float* __restrict__ cam, const float* __restrict__ theta,
       const float* __restrict__ va, const void* hp, const void* wp,
       int N, float* __restrict__ out) {
    __shared__ __align__(16) float su[SUB];
    __shared__ __align__(16) float sv[SUB];
    __shared__ __align__(16) float ss[SUB];
    __shared__ bool  isLast;
    __shared__ float red[128];

    const int tid  = threadIdx.x;
    const int warp = tid >> 5;
    const int lane = tid & 31;

    const int range = blockIdx.x >> 1;     // which point range
    const int chalf = blockIdx.x & 1;      // which 64-corner half

    // ---- Per-block fp32 camera setup (mirrors reference float32 pipeline) ----
    const float d2rf = 0.017453292519943295f;
    float rx = __fmul_rn(theta[0], d2rf);
    float ry = __fmul_rn(theta[1], d2rf);
    float rz = __fmul_rn(theta[2], d2rf);
    float cxa = cosf(rx), sxa = sinf(rx);
    float cya = cosf(ry), sya = sinf(ry);
    float cza = cosf(rz), sza = sinf(rz);
    // M = Ry @ Rx
    float M01 = __fmul_rn(sya, sxa), M02 = __fmul_rn(sya, cxa);
    float M11 = cxa,                 M12 = -sxa;
    float M20 = -sya, M21 = __fmul_rn(cya, sxa), M22 = __fmul_rn(cya, cxa);
    // R = Rz @ M  (row 2 of Rz is [0,0,1] -> row 2 of R = row 2 of M)
    const float R00 = __fmul_rn(cza, cya);
    const float R01 = __fsub_rn(__fmul_rn(cza, M01), __fmul_rn(sza, M11));
    const float R02 = __fsub_rn(__fmul_rn(cza, M02), __fmul_rn(sza, M12));
    const float R10 = __fmul_rn(sza, cya);
    const float R11 = __fadd_rn(__fmul_rn(sza, M01), __fmul_rn(cza, M11));
    const float R12 = __fadd_rn(__fmul_rn(sza, M02), __fmul_rn(cza, M12));
    const float R20 = M20, R21 = M21, R22 = M22;

    const float Hf = read_dim(hp), Wf = read_dim(wp);
    float vr = __fmul_rn(__fmul_rn(va[0], 0.5f), d2rf);
    const float f   = __fdiv_rn(-Hf, __fmul_rn(2.0f, tanf(vr)));
    const float kx0 = __fsub_rn(__fmul_rn(Wf, 0.5f), 0.5f);
    const float ky0 = __fsub_rn(__fmul_rn(Hf, 0.5f), 0.5f);
    const float camx = cam[0], camy = cam[1], camz = cam[2];

    // ---- This warp owns 8 corners as splatted f32x2 constants ----
    unsigned long long CX2[8], CY2[8], T12[8], M2[8];
    const int cbase = chalf * 64 + warp * 8;
#pragma unroll
    for (int k = 0; k < 8; k++) {
        int c = cbase + k;
        float ccx = dtc[2 * c], ccy = dtc[2 * c + 1];
        CX2[k] = pack2(ccx, ccx);
        CY2[k] = pack2(ccy, ccy);
        float t1 = __fadd_rn(__fmul_rn(ccx, ccx), __fmul_rn(ccy, ccy));
        T12[k] = pack2(t1, t1);
        M2[k]  = pack2(3.4e38f, 3.4e38f);
    }
    const unsigned long long N2 = pack2(-2.0f, -2.0f);

    // Contiguous point range for this block pair.
    const int ppb   = (N + NRANGE - 1) / NRANGE;
    const int start = range * ppb;
    const int stop  = min(N, start + ppb);

    for (int base = start; base < stop; base += SUB) {
        const int nval = min(SUB, stop - base);

        // Project directly from gmem (coalesced; constants live in registers).
        for (int i = tid; i < SUB; i += THREADS) {
            float u = 0.0f, vf = 0.0f, s = 3.0e38f;
            if (i < nval) {
                const float* pp = P + 3 * (base + i);
                float px = pp[0], py = pp[1], pz = pp[2];
                float tx = __fadd_rn(px, -camx);
                float ty = __fadd_rn(py, -camy);
                float tz = __fadd_rn(pz, -camz);
                float x = __fmaf_rn(tz, R02, __fmaf_rn(ty, R01, __fmul_rn(tx, R00)));
                float y = __fmaf_rn(tz, R12, __fmaf_rn(ty, R11, __fmul_rn(tx, R10)));
                float z = __fmaf_rn(tz, R22, __fmaf_rn(ty, R21, __fmul_rn(tx, R20)));
                float xp = __fdiv_rn(x, z);
                float yp = __fdiv_rn(y, z);
                u  = __fmaf_rn(f, xp, kx0);
                float v = __fmaf_rn(f, yp, ky0);
                vf = __fadd_rn(Hf, -v);
                s  = __fadd_rn(__fmul_rn(u, u), __fmul_rn(vf, vf));
            }
            su[i] = u; sv[i] = vf; ss[i] = s;
        }
        __syncthreads();

        // Inner loop: 2 points per iteration as native f32x2 operands.
        const unsigned long long* u64 = (const unsigned long long*)su;
        const unsigned long long* v64 = (const unsigned long long*)sv;
        const unsigned long long* s64 = (const unsigned long long*)ss;
#pragma unroll 4
        for (int j = lane; j < SUB / 2; j += 32) {
            unsigned long long u2 = u64[j];
            unsigned long long v2 = v64[j];
            unsigned long long s2 = s64[j];
#pragma unroll
            for (int k = 0; k < 8; k++)
                corner_step(M2[k], T12[k], CX2[k], CY2[k], u2, v2, s2, N2);
        }
        __syncthreads();
    }

    // Merge packed halves (even/odd points), then warp butterfly reduce.
    float m[8];
#pragma unroll
    for (int k = 0; k < 8; k++) {
        float lo, hi;
        unpack2(M2[k], lo, hi);
        m[k] = fminf(lo, hi);
    }
#pragma unroll
    for (int off = 16; off >= 1; off >>= 1) {
#pragma unroll
        for (int k = 0; k < 8; k++)
            m[k] = fminf(m[k], __shfl_xor_sync(0xFFFFFFFFu, m[k], off));
    }
    if (lane == 0) {
#pragma unroll
        for (int k = 0; k < 8; k++)
            atomicMax(&g_cmax[cbase + k], ~fenc(m[k]));   // inverted key: init 0 is safe
    }

    // Last block: final deterministic sum + self-restore scratch to zero.
    __threadfence();
    __syncthreads();
    if (tid == 0) {
        unsigned old = atomicAdd(&g_ctr, 1u);
        isLast = (old == gridDim.x - 1u);
    }
    __syncthreads();
    if (isLast) {
        if (tid < 128) {
            red[tid] = fdec(~g_cmax[tid]);
            g_cmax[tid] = 0u;               // restore for next (graph) replay
        }
        if (tid == 0) g_ctr = 0u;
        __syncthreads();
        for (int off = 64; off > 0; off >>= 1) {
            if (tid < off) red[tid] += red[tid + off];
            __syncthreads();
        }
        if (tid == 0) out[0] = red[0];
    }
}

extern "C" void kernel_launch(void* const* d_in, const int* in_sizes, int n_in,
                              void* d_out, int out_size) {
    const float* PntCld = (const float*)d_in[0];
    const float* dtcCor = (const float*)d_in[1];
    const float* cam    = (const float*)d_in[2];
    const float* theta  = (const float*)d_in[3];
    const float* va     = (const float*)d_in[4];
    const void*  hp     = d_in[5];
    const void*  wp     = d_in[6];

    int N = in_sizes[0] / 3;

    k_main<<<GRID, THREADS>>>(PntCld, dtcCor, cam, theta, va, hp, wp,
                              N, (float*)d_out);
}